// round 1
// baseline (speedup 1.0000x reference)
#include <cuda_runtime.h>
#include <math.h>
#include <stddef.h>

// Problem constants
#define T_LEN 256
#define B_SZ  256
#define H_DIM 512
#define R_ROWS 768          // 3 texts * 256 batch
#define G_COLS 2048         // 4*H
#define M_ALL  196608       // T_LEN * R_ROWS
#define H5 102              // H/5

// ---------------- static device scratch (no allocations allowed) ------------
__device__ float d_Xbuf[100663296];   // [T][768][512] layer input
__device__ float d_Ybuf[100663296];   // [T][768][512] layer output
__device__ float d_Gbuf[402653184];   // [T][768][2048] precomputed x@Wx + b
__device__ float d_cst[393216];       // [768][512] cell state
__device__ float d_rbuf[393216];      // [256][1536]
__device__ float d_h1buf[262144];     // [256][1024]
__device__ float d_h2buf[26112];      // [256][102]

// ---------------- embedding gather ------------------------------------------
__global__ void clstm_embed(const int* __restrict__ t1, const int* __restrict__ t2,
                            const int* __restrict__ t3, const float* __restrict__ emb,
                            float* __restrict__ X) {
    int row = blockIdx.x;            // 0..767
    int t   = blockIdx.y;            // 0..255
    int text = row >> 8, b = row & 255;
    const int* tp = (text == 0) ? t1 : (text == 1 ? t2 : t3);
    int tok = tp[b * T_LEN + t];
    const float4* src = (const float4*)(emb + (size_t)tok * H_DIM);
    float4* dst = (float4*)(X + ((size_t)t * R_ROWS + row) * H_DIM);
    dst[threadIdx.x] = src[threadIdx.x];   // 128 threads * float4 = 512 floats
}

// ---------------- big fp32 GEMM: C[M,N] = A[M,K]*Bm[K,N] + bias[N] ----------
// 128x128 block tile, K-step 16, 256 threads, 8x8 per thread.
// Requires M%128==0, N%128==0, K%16==0 (true for the gate GEMM).
__global__ void __launch_bounds__(256)
clstm_gemm_bias(const float* __restrict__ A, const float* __restrict__ Bm,
                const float* __restrict__ bias, float* __restrict__ C,
                int M, int N, int K) {
    __shared__ float As[16][132];
    __shared__ float Bs[16][128];
    int bn = blockIdx.x * 128;
    int bm = blockIdx.y * 128;
    int tid = threadIdx.x;
    int tx = tid & 15, ty = tid >> 4;
    float acc[8][8];
#pragma unroll
    for (int i = 0; i < 8; i++)
#pragma unroll
        for (int j = 0; j < 8; j++) acc[i][j] = 0.f;

    for (int k0 = 0; k0 < K; k0 += 16) {
#pragma unroll
        for (int i = 0; i < 2; i++) {
            int idx = tid + i * 256;           // 0..511
            int r = idx >> 2, c4 = (idx & 3) << 2;
            float4 v = *(const float4*)(A + (size_t)(bm + r) * K + k0 + c4);
            As[c4 + 0][r] = v.x; As[c4 + 1][r] = v.y;
            As[c4 + 2][r] = v.z; As[c4 + 3][r] = v.w;
        }
#pragma unroll
        for (int i = 0; i < 2; i++) {
            int idx = tid + i * 256;
            int kr = idx >> 5, nc = (idx & 31) << 2;
            *(float4*)(&Bs[kr][nc]) =
                *(const float4*)(Bm + (size_t)(k0 + kr) * N + bn + nc);
        }
        __syncthreads();
#pragma unroll
        for (int kk = 0; kk < 16; kk++) {
            float a[8], bb[8];
#pragma unroll
            for (int i = 0; i < 8; i++) a[i] = As[kk][ty * 8 + i];
#pragma unroll
            for (int j = 0; j < 8; j++) bb[j] = Bs[kk][tx * 8 + j];
#pragma unroll
            for (int i = 0; i < 8; i++)
#pragma unroll
                for (int j = 0; j < 8; j++) acc[i][j] += a[i] * bb[j];
        }
        __syncthreads();
    }
#pragma unroll
    for (int i = 0; i < 8; i++) {
        size_t rowoff = (size_t)(bm + ty * 8 + i) * N + bn;
#pragma unroll
        for (int j = 0; j < 8; j++)
            C[rowoff + tx * 8 + j] = acc[i][j] + bias[bn + tx * 8 + j];
    }
}

// ---------------- fused recurrent step --------------------------------------
// grid (16, 8): blockIdx.x = 32-hcol block (covers gate cols i/f/g/o for those
// 32 h columns), blockIdx.y = 96-row block of the 768 batch rows.
// gates_tile = hprev[96,512] @ Wh[:, 4 strips of 32] + G[t] (precomputed),
// then LSTM elementwise update, fused.
// dynamic smem: gates 96*128 + As 16*100 + Bs 16*128 = 15936 floats = 63744 B
#define STEP_SMEM 63744
__global__ void __launch_bounds__(256)
clstm_step(const float* __restrict__ Gt, const float* __restrict__ hprev,
           const float* __restrict__ Wh, float* __restrict__ cst,
           float* __restrict__ hout, int t0) {
    extern __shared__ float sm[];
    float* gsm = sm;                 // [96][128]
    float* As  = sm + 96 * 128;      // [16][100]
    float* Bs  = As + 16 * 100;      // [16][128]
    int cb = blockIdx.x;             // h-col block (32 cols)
    int bm = blockIdx.y * 96;        // row base
    int tid = threadIdx.x;
    int tx = tid & 15, ty = tid >> 4;

    float acc[6][8];
#pragma unroll
    for (int i = 0; i < 6; i++)
#pragma unroll
        for (int j = 0; j < 8; j++) acc[i][j] = 0.f;

    if (!t0) {
        for (int k0 = 0; k0 < H_DIM; k0 += 16) {
#pragma unroll
            for (int i = 0; i < 6; i++) {          // 96x16 = 1536 scalars
                int idx = tid + i * 256;
                int r = idx >> 4, kc = idx & 15;
                As[kc * 100 + r] = hprev[(size_t)(bm + r) * H_DIM + k0 + kc];
            }
#pragma unroll
            for (int i = 0; i < 2; i++) {          // 16x128 via float4
                int idx = tid + i * 256;
                int kr = idx >> 5, lc = (idx & 31) << 2;
                int gate = lc >> 5, w = lc & 31;
                *(float4*)(Bs + kr * 128 + lc) =
                    *(const float4*)(Wh + (size_t)(k0 + kr) * G_COLS +
                                     gate * H_DIM + cb * 32 + w);
            }
            __syncthreads();
#pragma unroll
            for (int kk = 0; kk < 16; kk++) {
                float a[6], bb[8];
#pragma unroll
                for (int i = 0; i < 6; i++) a[i] = As[kk * 100 + ty * 6 + i];
#pragma unroll
                for (int j = 0; j < 8; j++) bb[j] = Bs[kk * 128 + tx * 8 + j];
#pragma unroll
                for (int i = 0; i < 6; i++)
#pragma unroll
                    for (int j = 0; j < 8; j++) acc[i][j] += a[i] * bb[j];
            }
            __syncthreads();
        }
    }
    // stash gate partials
#pragma unroll
    for (int i = 0; i < 6; i++)
#pragma unroll
        for (int j = 0; j < 8; j++)
            gsm[(ty * 6 + i) * 128 + tx * 8 + j] = acc[i][j];
    __syncthreads();

    // epilogue: 96 rows x 32 h-cols = 3072 elements, 12 per thread
#pragma unroll
    for (int q = 0; q < 12; q++) {
        int e = tid + q * 256;
        int r = e >> 5, j = e & 31;
        int grow = bm + r;
        int hc = cb * 32 + j;
        size_t gbase = (size_t)grow * G_COLS;
        float xi = gsm[r * 128 +       j] + Gt[gbase +            hc];
        float xf = gsm[r * 128 +  32 + j] + Gt[gbase +  H_DIM   + hc];
        float xg = gsm[r * 128 +  64 + j] + Gt[gbase + 2*H_DIM  + hc];
        float xo = gsm[r * 128 +  96 + j] + Gt[gbase + 3*H_DIM  + hc];
        float ig = 1.f / (1.f + expf(-xi));
        float fg = 1.f / (1.f + expf(-xf));
        float gg = tanhf(xg);
        float og = 1.f / (1.f + expf(-xo));
        size_t cidx = (size_t)grow * H_DIM + hc;
        float cn = fg * cst[cidx] + ig * gg;
        cst[cidx] = cn;
        hout[cidx] = og * tanhf(cn);
    }
}

// ---------------- head kernels ----------------------------------------------
__global__ void clstm_gather_r(const float* __restrict__ Ytop, float* __restrict__ r) {
    int b = blockIdx.x, i = blockIdx.y, h = threadIdx.x;   // block 512
    r[(size_t)b * 1536 + i * H_DIM + h] =
        Ytop[((size_t)(T_LEN - 1) * R_ROWS + i * B_SZ + b) * H_DIM + h];
}

// batchnorm over batch dim (M=256 rows == blockDim), one block per column
__global__ void clstm_bn(float* __restrict__ x, const float* __restrict__ gamma,
                         const float* __restrict__ beta, int N) {
    __shared__ float s1[256], s2[256];
    int col = blockIdx.x;
    float v = x[(size_t)threadIdx.x * N + col];
    s1[threadIdx.x] = v;
    s2[threadIdx.x] = v * v;
    __syncthreads();
    for (int s = 128; s > 0; s >>= 1) {
        if (threadIdx.x < s) {
            s1[threadIdx.x] += s1[threadIdx.x + s];
            s2[threadIdx.x] += s2[threadIdx.x + s];
        }
        __syncthreads();
    }
    float m = s1[0] * (1.f / 256.f);
    float var = s2[0] * (1.f / 256.f) - m * m;
    float inv = rsqrtf(var + 1e-3f);
    x[(size_t)threadIdx.x * N + col] = gamma[col] * (v - m) * inv + beta[col];
}

// small head GEMM: C[M,N] = act(A[M,K] @ W[K,N] + bias), 16 rows per block
__global__ void clstm_gemm_head(const float* __restrict__ A, const float* __restrict__ W,
                                const float* __restrict__ bias, float* __restrict__ C,
                                int K, int N, int act) {
    int n = blockIdx.x * 128 + threadIdx.x;
    int m0 = blockIdx.y * 16;
    if (n >= N) return;
    float s[16];
#pragma unroll
    for (int mm = 0; mm < 16; mm++) s[mm] = bias[n];
    for (int k = 0; k < K; k++) {
        float w = W[(size_t)k * N + n];
#pragma unroll
        for (int mm = 0; mm < 16; mm++)
            s[mm] += A[(size_t)(m0 + mm) * K + k] * w;
    }
    const float alpha = 1.6732632423543772f, scale = 1.0507009873554805f;
#pragma unroll
    for (int mm = 0; mm < 16; mm++) {
        float v = s[mm];
        if (act) v = scale * (v > 0.f ? v : alpha * expm1f(v));
        C[(size_t)(m0 + mm) * N + n] = v;
    }
}

// ---------------- launch ------------------------------------------------------
extern "C" void kernel_launch(void* const* d_in, const int* in_sizes, int n_in,
                              void* d_out, int out_size) {
    const int*   t1   = (const int*)d_in[0];
    const int*   t2   = (const int*)d_in[1];
    const int*   t3   = (const int*)d_in[2];
    const float* emb  = (const float*)d_in[3];
    const float* Wx   = (const float*)d_in[4];
    const float* Wh   = (const float*)d_in[5];
    const float* bb   = (const float*)d_in[6];
    const float* g1   = (const float*)d_in[7];
    const float* be1  = (const float*)d_in[8];
    const float* W1   = (const float*)d_in[9];
    const float* bd1  = (const float*)d_in[10];
    const float* g2   = (const float*)d_in[11];
    const float* be2  = (const float*)d_in[12];
    const float* W2   = (const float*)d_in[13];
    const float* bd2  = (const float*)d_in[14];
    const float* g3   = (const float*)d_in[15];
    const float* be3  = (const float*)d_in[16];
    const float* W3   = (const float*)d_in[17];
    const float* bd3  = (const float*)d_in[18];
    float* out = (float*)d_out;

    float *X, *Y, *G, *C, *R, *H1, *H2;
    cudaGetSymbolAddress((void**)&X,  d_Xbuf);
    cudaGetSymbolAddress((void**)&Y,  d_Ybuf);
    cudaGetSymbolAddress((void**)&G,  d_Gbuf);
    cudaGetSymbolAddress((void**)&C,  d_cst);
    cudaGetSymbolAddress((void**)&R,  d_rbuf);
    cudaGetSymbolAddress((void**)&H1, d_h1buf);
    cudaGetSymbolAddress((void**)&H2, d_h2buf);

    cudaFuncSetAttribute(clstm_step, cudaFuncAttributeMaxDynamicSharedMemorySize,
                         STEP_SMEM);

    // 1) embedding -> X  [T][768][512]
    clstm_embed<<<dim3(R_ROWS, T_LEN), 128>>>(t1, t2, t3, emb, X);

    float* inb = X;
    float* outb = Y;
    for (int l = 0; l < 3; l++) {
        // 2) G = inb @ Wx_l + b_l   (batched over all T and all 3 texts)
        clstm_gemm_bias<<<dim3(G_COLS / 128, M_ALL / 128), 256>>>(
            inb, Wx + (size_t)l * H_DIM * G_COLS, bb + (size_t)l * G_COLS, G,
            M_ALL, G_COLS, H_DIM);
        // 3) reset cell state
        cudaMemsetAsync(C, 0, (size_t)R_ROWS * H_DIM * sizeof(float), 0);
        // 4) 256 recurrent steps (fused GEMM + LSTM update)
        for (int t = 0; t < T_LEN; t++) {
            clstm_step<<<dim3(16, 8), 256, STEP_SMEM>>>(
                G + (size_t)t * R_ROWS * G_COLS,
                outb + (size_t)(t > 0 ? t - 1 : 0) * R_ROWS * H_DIM,
                Wh + (size_t)l * H_DIM * G_COLS, C,
                outb + (size_t)t * R_ROWS * H_DIM, t == 0 ? 1 : 0);
        }
        float* tmp = inb; inb = outb; outb = tmp;   // next layer reads this output
    }
    // top-layer outputs are now in `inb`

    // 5) head: r = concat(last hidden of 3 texts) [256,1536]
    clstm_gather_r<<<dim3(B_SZ, 3), H_DIM>>>(inb, R);
    clstm_bn<<<1536, 256>>>(R, g1, be1, 1536);
    clstm_gemm_head<<<dim3(8, 16), 128>>>(R, W1, bd1, H1, 1536, 1024, 1);
    clstm_bn<<<1024, 256>>>(H1, g2, be2, 1024);
    clstm_gemm_head<<<dim3(1, 16), 128>>>(H1, W2, bd2, H2, 1024, H5, 1);
    clstm_bn<<<H5, 256>>>(H2, g3, be3, H5);
    clstm_gemm_head<<<dim3(1, 16), 128>>>(H2, W3, bd3, out, H5, 4, 0);
}

// round 2
// speedup vs baseline: 1.0111x; 1.0111x over previous
#include <cuda_runtime.h>
#include <math.h>
#include <stddef.h>

// Problem constants
#define T_LEN 256
#define B_SZ  256
#define H_DIM 512
#define R_ROWS 768          // 3 texts * 256 batch
#define G_COLS 2048         // 4*H
#define M_ALL  196608       // T_LEN * R_ROWS
#define H5 102              // H/5

// ---------------- static device scratch (no allocations allowed) ------------
__device__ float d_Xbuf[100663296];   // [T][768][512] layer input
__device__ float d_Ybuf[100663296];   // [T][768][512] layer output
__device__ float d_Gbuf[402653184];   // [T][768][2048] precomputed x@Wx + b
__device__ float d_cst[393216];       // [768][512] cell state
__device__ float d_rbuf[393216];      // [256][1536]
__device__ float d_h1buf[262144];     // [256][1024]
__device__ float d_h2buf[26112];      // [256][102]

// ---------------- embedding gather ------------------------------------------
__global__ void clstm_embed(const int* __restrict__ t1, const int* __restrict__ t2,
                            const int* __restrict__ t3, const float* __restrict__ emb,
                            float* __restrict__ X) {
    int row = blockIdx.x;            // 0..767
    int t   = blockIdx.y;            // 0..255
    int text = row >> 8, b = row & 255;
    const int* tp = (text == 0) ? t1 : (text == 1 ? t2 : t3);
    int tok = tp[b * T_LEN + t];
    const float4* src = (const float4*)(emb + (size_t)tok * H_DIM);
    float4* dst = (float4*)(X + ((size_t)t * R_ROWS + row) * H_DIM);
    dst[threadIdx.x] = src[threadIdx.x];   // 128 threads * float4 = 512 floats
}

// ---------------- big fp32 GEMM: C[M,N] = A[M,K]*Bm[K,N] + bias[N] ----------
// 128x128 block tile, K-step 16, 256 threads, 8x8 per thread. (near roofline)
__global__ void __launch_bounds__(256)
clstm_gemm_bias(const float* __restrict__ A, const float* __restrict__ Bm,
                const float* __restrict__ bias, float* __restrict__ C,
                int M, int N, int K) {
    __shared__ float As[16][132];
    __shared__ float Bs[16][128];
    int bn = blockIdx.x * 128;
    int bm = blockIdx.y * 128;
    int tid = threadIdx.x;
    int tx = tid & 15, ty = tid >> 4;
    float acc[8][8];
#pragma unroll
    for (int i = 0; i < 8; i++)
#pragma unroll
        for (int j = 0; j < 8; j++) acc[i][j] = 0.f;

    for (int k0 = 0; k0 < K; k0 += 16) {
#pragma unroll
        for (int i = 0; i < 2; i++) {
            int idx = tid + i * 256;           // 0..511
            int r = idx >> 2, c4 = (idx & 3) << 2;
            float4 v = *(const float4*)(A + (size_t)(bm + r) * K + k0 + c4);
            As[c4 + 0][r] = v.x; As[c4 + 1][r] = v.y;
            As[c4 + 2][r] = v.z; As[c4 + 3][r] = v.w;
        }
#pragma unroll
        for (int i = 0; i < 2; i++) {
            int idx = tid + i * 256;
            int kr = idx >> 5, nc = (idx & 31) << 2;
            *(float4*)(&Bs[kr][nc]) =
                *(const float4*)(Bm + (size_t)(k0 + kr) * N + bn + nc);
        }
        __syncthreads();
#pragma unroll
        for (int kk = 0; kk < 16; kk++) {
            float a[8], bb[8];
#pragma unroll
            for (int i = 0; i < 8; i++) a[i] = As[kk][ty * 8 + i];
#pragma unroll
            for (int j = 0; j < 8; j++) bb[j] = Bs[kk][tx * 8 + j];
#pragma unroll
            for (int i = 0; i < 8; i++)
#pragma unroll
                for (int j = 0; j < 8; j++) acc[i][j] += a[i] * bb[j];
        }
        __syncthreads();
    }
#pragma unroll
    for (int i = 0; i < 8; i++) {
        size_t rowoff = (size_t)(bm + ty * 8 + i) * N + bn;
#pragma unroll
        for (int j = 0; j < 8; j++)
            C[rowoff + tx * 8 + j] = acc[i][j] + bias[bn + tx * 8 + j];
    }
}

// ---------------- fused recurrent step (v2: 32x32 tiles, 384 CTAs) ----------
// grid (16, 24): blockIdx.x = 32-hcol block (4 gate strips of 32 cols),
// blockIdx.y = 32-row block of the 768 batch rows.
// Per CTA: gates[32,128] = hprev[32,512] @ Wh[:,strips] + Gt, then LSTM update.
// 256 threads: lane = tid&31 owns 4 gate-cols (lane*4), wy = tid>>5 owns 4 rows.
// Inner loop: 2x LDS.128 + 16 FFMA per kk. Smem (16KB) unioned: As/Bs then gsm.
__global__ void __launch_bounds__(256)
clstm_step(const float* __restrict__ Gt, const float* __restrict__ hprev,
           const float* __restrict__ Wh, float* __restrict__ cst,
           float* __restrict__ hout, int t0) {
    __shared__ float sm[4096];       // max(32*128 gsm, 576 As + 2048 Bs)
    float* As = sm;                  // [16][36]  (k-major, padded)
    float* Bs = sm + 576;            // [16][128]
    int cb = blockIdx.x;             // h-col block (32 cols)
    int bm = blockIdx.y * 32;        // row base
    int tid = threadIdx.x;
    int lane = tid & 31, wy = tid >> 5;

    float acc[4][4];
#pragma unroll
    for (int i = 0; i < 4; i++)
#pragma unroll
        for (int j = 0; j < 4; j++) acc[i][j] = 0.f;

    if (!t0) {
        for (int k0 = 0; k0 < H_DIM; k0 += 16) {
            // As: 32 rows x 16 k -> transposed, 128 float4 loads (tid<128)
            if (tid < 128) {
                int r = tid >> 2, c4 = (tid & 3) << 2;
                float4 v = *(const float4*)(hprev + (size_t)(bm + r) * H_DIM + k0 + c4);
                As[(c4 + 0) * 36 + r] = v.x;
                As[(c4 + 1) * 36 + r] = v.y;
                As[(c4 + 2) * 36 + r] = v.z;
                As[(c4 + 3) * 36 + r] = v.w;
            }
            // Bs: 16 k x 128 gate-cols, 512 float4 loads
#pragma unroll
            for (int i = 0; i < 2; i++) {
                int idx = tid + i * 256;            // 0..511
                int kr = idx >> 5, lc = (idx & 31) << 2;
                int gate = lc >> 5, w = lc & 31;
                *(float4*)(Bs + kr * 128 + lc) =
                    *(const float4*)(Wh + (size_t)(k0 + kr) * G_COLS +
                                     gate * H_DIM + cb * 32 + w);
            }
            __syncthreads();
#pragma unroll
            for (int kk = 0; kk < 16; kk++) {
                float4 a = *(const float4*)(As + kk * 36 + wy * 4);   // broadcast
                float4 b = *(const float4*)(Bs + kk * 128 + lane * 4);
                acc[0][0] += a.x * b.x; acc[0][1] += a.x * b.y;
                acc[0][2] += a.x * b.z; acc[0][3] += a.x * b.w;
                acc[1][0] += a.y * b.x; acc[1][1] += a.y * b.y;
                acc[1][2] += a.y * b.z; acc[1][3] += a.y * b.w;
                acc[2][0] += a.z * b.x; acc[2][1] += a.z * b.y;
                acc[2][2] += a.z * b.z; acc[2][3] += a.z * b.w;
                acc[3][0] += a.w * b.x; acc[3][1] += a.w * b.y;
                acc[3][2] += a.w * b.z; acc[3][3] += a.w * b.w;
            }
            __syncthreads();
        }
    }
    // stash gate partials into gsm (reuses As/Bs space)
    float* gsm = sm;                 // [32][128]
#pragma unroll
    for (int i = 0; i < 4; i++)
        *(float4*)(gsm + (wy * 4 + i) * 128 + lane * 4) =
            make_float4(acc[i][0], acc[i][1], acc[i][2], acc[i][3]);
    __syncthreads();

    // epilogue: 32 rows x 32 h-cols = 1024 elements, 4 per thread
#pragma unroll
    for (int q = 0; q < 4; q++) {
        int e = tid + q * 256;
        int r = e >> 5, j = e & 31;
        int grow = bm + r;
        int hc = cb * 32 + j;
        size_t gbase = (size_t)grow * G_COLS;
        float xi = gsm[r * 128 +       j] + Gt[gbase +             hc];
        float xf = gsm[r * 128 +  32 + j] + Gt[gbase +   H_DIM  + hc];
        float xg = gsm[r * 128 +  64 + j] + Gt[gbase + 2*H_DIM  + hc];
        float xo = gsm[r * 128 +  96 + j] + Gt[gbase + 3*H_DIM  + hc];
        float ig = 1.f / (1.f + expf(-xi));
        float fg = 1.f / (1.f + expf(-xf));
        float gg = tanhf(xg);
        float og = 1.f / (1.f + expf(-xo));
        size_t cidx = (size_t)grow * H_DIM + hc;
        float cn = fg * cst[cidx] + ig * gg;
        cst[cidx] = cn;
        hout[cidx] = og * tanhf(cn);
    }
}

// ---------------- head kernels ----------------------------------------------
__global__ void clstm_gather_r(const float* __restrict__ Ytop, float* __restrict__ r) {
    int b = blockIdx.x, i = blockIdx.y, h = threadIdx.x;   // block 512
    r[(size_t)b * 1536 + i * H_DIM + h] =
        Ytop[((size_t)(T_LEN - 1) * R_ROWS + i * B_SZ + b) * H_DIM + h];
}

// batchnorm over batch dim (M=256 rows == blockDim), one block per column
__global__ void clstm_bn(float* __restrict__ x, const float* __restrict__ gamma,
                         const float* __restrict__ beta, int N) {
    __shared__ float s1[256], s2[256];
    int col = blockIdx.x;
    float v = x[(size_t)threadIdx.x * N + col];
    s1[threadIdx.x] = v;
    s2[threadIdx.x] = v * v;
    __syncthreads();
    for (int s = 128; s > 0; s >>= 1) {
        if (threadIdx.x < s) {
            s1[threadIdx.x] += s1[threadIdx.x + s];
            s2[threadIdx.x] += s2[threadIdx.x + s];
        }
        __syncthreads();
    }
    float m = s1[0] * (1.f / 256.f);
    float var = s2[0] * (1.f / 256.f) - m * m;
    float inv = rsqrtf(var + 1e-3f);
    x[(size_t)threadIdx.x * N + col] = gamma[col] * (v - m) * inv + beta[col];
}

// small head GEMM: C[M,N] = act(A[M,K] @ W[K,N] + bias), 16 rows per block
__global__ void clstm_gemm_head(const float* __restrict__ A, const float* __restrict__ W,
                                const float* __restrict__ bias, float* __restrict__ C,
                                int K, int N, int act) {
    int n = blockIdx.x * 128 + threadIdx.x;
    int m0 = blockIdx.y * 16;
    if (n >= N) return;
    float s[16];
#pragma unroll
    for (int mm = 0; mm < 16; mm++) s[mm] = bias[n];
    for (int k = 0; k < K; k++) {
        float w = W[(size_t)k * N + n];
#pragma unroll
        for (int mm = 0; mm < 16; mm++)
            s[mm] += A[(size_t)(m0 + mm) * K + k] * w;
    }
    const float alpha = 1.6732632423543772f, scale = 1.0507009873554805f;
#pragma unroll
    for (int mm = 0; mm < 16; mm++) {
        float v = s[mm];
        if (act) v = scale * (v > 0.f ? v : alpha * expm1f(v));
        C[(size_t)(m0 + mm) * N + n] = v;
    }
}

// ---------------- launch ------------------------------------------------------
extern "C" void kernel_launch(void* const* d_in, const int* in_sizes, int n_in,
                              void* d_out, int out_size) {
    const int*   t1   = (const int*)d_in[0];
    const int*   t2   = (const int*)d_in[1];
    const int*   t3   = (const int*)d_in[2];
    const float* emb  = (const float*)d_in[3];
    const float* Wx   = (const float*)d_in[4];
    const float* Wh   = (const float*)d_in[5];
    const float* bb   = (const float*)d_in[6];
    const float* g1   = (const float*)d_in[7];
    const float* be1  = (const float*)d_in[8];
    const float* W1   = (const float*)d_in[9];
    const float* bd1  = (const float*)d_in[10];
    const float* g2   = (const float*)d_in[11];
    const float* be2  = (const float*)d_in[12];
    const float* W2   = (const float*)d_in[13];
    const float* bd2  = (const float*)d_in[14];
    const float* g3   = (const float*)d_in[15];
    const float* be3  = (const float*)d_in[16];
    const float* W3   = (const float*)d_in[17];
    const float* bd3  = (const float*)d_in[18];
    float* out = (float*)d_out;

    float *X, *Y, *G, *C, *R, *H1, *H2;
    cudaGetSymbolAddress((void**)&X,  d_Xbuf);
    cudaGetSymbolAddress((void**)&Y,  d_Ybuf);
    cudaGetSymbolAddress((void**)&G,  d_Gbuf);
    cudaGetSymbolAddress((void**)&C,  d_cst);
    cudaGetSymbolAddress((void**)&R,  d_rbuf);
    cudaGetSymbolAddress((void**)&H1, d_h1buf);
    cudaGetSymbolAddress((void**)&H2, d_h2buf);

    // 1) embedding -> X  [T][768][512]
    clstm_embed<<<dim3(R_ROWS, T_LEN), 128>>>(t1, t2, t3, emb, X);

    float* inb = X;
    float* outb = Y;
    for (int l = 0; l < 3; l++) {
        // 2) G = inb @ Wx_l + b_l   (batched over all T and all 3 texts)
        clstm_gemm_bias<<<dim3(G_COLS / 128, M_ALL / 128), 256>>>(
            inb, Wx + (size_t)l * H_DIM * G_COLS, bb + (size_t)l * G_COLS, G,
            M_ALL, G_COLS, H_DIM);
        // 3) reset cell state
        cudaMemsetAsync(C, 0, (size_t)R_ROWS * H_DIM * sizeof(float), 0);
        // 4) 256 recurrent steps (fused GEMM + LSTM update)
        for (int t = 0; t < T_LEN; t++) {
            clstm_step<<<dim3(16, 24), 256>>>(
                G + (size_t)t * R_ROWS * G_COLS,
                outb + (size_t)(t > 0 ? t - 1 : 0) * R_ROWS * H_DIM,
                Wh + (size_t)l * H_DIM * G_COLS, C,
                outb + (size_t)t * R_ROWS * H_DIM, t == 0 ? 1 : 0);
        }
        float* tmp = inb; inb = outb; outb = tmp;   // next layer reads this output
    }
    // top-layer outputs are now in `inb`

    // 5) head: r = concat(last hidden of 3 texts) [256,1536]
    clstm_gather_r<<<dim3(B_SZ, 3), H_DIM>>>(inb, R);
    clstm_bn<<<1536, 256>>>(R, g1, be1, 1536);
    clstm_gemm_head<<<dim3(8, 16), 128>>>(R, W1, bd1, H1, 1536, 1024, 1);
    clstm_bn<<<1024, 256>>>(H1, g2, be2, 1024);
    clstm_gemm_head<<<dim3(1, 16), 128>>>(H1, W2, bd2, H2, 1024, H5, 1);
    clstm_bn<<<H5, 256>>>(H2, g3, be3, H5);
    clstm_gemm_head<<<dim3(1, 16), 128>>>(H2, W3, bd3, out, H5, 4, 0);
}